// round 3
// baseline (speedup 1.0000x reference)
#include <cuda_runtime.h>
#include <cstdint>

// Problem constants
constexpr int N_IN   = 16384;          // samples per row
constexpr int T_OUT  = 8195;           // cA (=cD) length: ((N+13)-8)/2+1
constexpr int OUTROW = 2 * T_OUT;      // 16390

constexpr int THREADS = 256;
constexpr int TPT     = 4;             // t-values per thread
constexpr int TT      = THREADS * TPT; // 1024 t per tile
constexpr int TILES   = (T_OUT + TT - 1) / TT;  // 9
constexpr int SLEN    = TT + 4;        // per-parity smem entries needed (incl. float4 overread)

// sig[i] = x_ext[i+1] with symmetric pad of 7 each side.
// interior: x[i-6]; left (i<6): x[5-i]; right (i>=N+6): x[2N+5-i]
__device__ __forceinline__ int map_sig(int i) {
    int m = i - 6;
    m = (m < 0) ? (-1 - m) : m;
    m = (m >= N_IN) ? (2 * N_IN - 1 - m) : m;
    return m;
}

__global__ __launch_bounds__(THREADS) void dwt_kernel(const float* __restrict__ x,
                                                      float* __restrict__ out)
{
    __shared__ __align__(16) float se[SLEN + 4];   // sig[2u]   (even taps)
    __shared__ __align__(16) float so[SLEN + 4];   // sig[2u+1] (odd taps)

    const int row = blockIdx.y;
    const int t0  = blockIdx.x * TT;
    const float* __restrict__ xr = x + (size_t)row * N_IN;

    // ---- cooperative deinterleaved fill ----
    const int s0 = 2 * t0;   // first sig index this tile needs
    for (int i = threadIdx.x; i < SLEN; i += THREADS) {
        const int g  = s0 + 2 * i;
        const int m0 = map_sig(g);
        const int m1 = map_sig(g + 1);
        se[i] = __ldg(xr + m0);
        so[i] = __ldg(xr + m1);
    }
    __syncthreads();

    // time-reversed filters (compile-time immediates)
    // LO[j] = DEC_LO[7-j] ; HI[j] = (-1)^j * DEC_LO[j]
    const float LO[8] = {  0.23037781330885523f,  0.7148465705525415f,
                           0.6308807679295904f,  -0.02798376941698385f,
                          -0.18703481171888114f,  0.030841381835986965f,
                           0.032883011666982945f,-0.010597401784997278f };
    const float HI[8] = { -0.010597401784997278f,-0.032883011666982945f,
                           0.030841381835986965f, 0.18703481171888114f,
                          -0.02798376941698385f, -0.6308807679295904f,
                           0.7148465705525415f,  -0.23037781330885523f };

    const int u = TPT * threadIdx.x;     // local t offset (multiple of 4)

    // conflict-free vector loads from smem
    const float4 ev0 = *reinterpret_cast<const float4*>(&se[u]);
    const float4 ev1 = *reinterpret_cast<const float4*>(&se[u + 4]);
    const float4 od0 = *reinterpret_cast<const float4*>(&so[u]);
    const float4 od1 = *reinterpret_cast<const float4*>(&so[u + 4]);
    const float e[8] = { ev0.x, ev0.y, ev0.z, ev0.w, ev1.x, ev1.y, ev1.z, ev1.w };
    const float o[8] = { od0.x, od0.y, od0.z, od0.w, od1.x, od1.y, od1.z, od1.w };

    float ca[TPT], cd[TPT];
    #pragma unroll
    for (int v = 0; v < TPT; v++) {
        float a = 0.f, d = 0.f;
        #pragma unroll
        for (int c = 0; c < 4; c++) {
            // sig[2t + 2c]   -> e[v+c]
            // sig[2t + 2c+1] -> o[v+c]
            a = fmaf(LO[2*c    ], e[v + c], a);
            a = fmaf(LO[2*c + 1], o[v + c], a);
            d = fmaf(HI[2*c    ], e[v + c], d);
            d = fmaf(HI[2*c + 1], o[v + c], d);
        }
        ca[v] = a; cd[v] = d;
    }

    float* __restrict__ orow = out + (size_t)row * OUTROW;
    const int t = t0 + u;
    if (t + 3 < T_OUT) {
        // cA: 8B-aligned float2 stores (row*OUTROW even, t even)
        *reinterpret_cast<float2*>(&orow[t    ]) = make_float2(ca[0], ca[1]);
        *reinterpret_cast<float2*>(&orow[t + 2]) = make_float2(ca[2], ca[3]);
        // cD offsets are odd (T_OUT odd) -> scalar stores
        orow[T_OUT + t    ] = cd[0];
        orow[T_OUT + t + 1] = cd[1];
        orow[T_OUT + t + 2] = cd[2];
        orow[T_OUT + t + 3] = cd[3];
    } else {
        #pragma unroll
        for (int v = 0; v < TPT; v++) {
            if (t + v < T_OUT) {
                orow[t + v]         = ca[v];
                orow[T_OUT + t + v] = cd[v];
            }
        }
    }
}

extern "C" void kernel_launch(void* const* d_in, const int* in_sizes, int n_in,
                              void* d_out, int out_size)
{
    const float* x = (const float*)d_in[0];
    float* out = (float*)d_out;
    const int rows = in_sizes[0] / N_IN;   // 4096
    dim3 grid(TILES, rows);
    dwt_kernel<<<grid, THREADS>>>(x, out);
}

// round 4
// speedup vs baseline: 1.2493x; 1.2493x over previous
#include <cuda_runtime.h>
#include <cstdint>

// Problem constants
constexpr int N_IN   = 16384;          // samples per row
constexpr int T_OUT  = 8195;           // cA (=cD) length: ((N+13)-8)/2+1
constexpr int OUTROW = 2 * T_OUT;      // 16390

constexpr int THREADS = 256;
constexpr int TPT     = 4;             // t-values per thread
constexpr int TT      = THREADS * TPT; // 1024 t per tile
constexpr int TILES   = (T_OUT + TT - 1) / TT;  // 9
constexpr int SLEN    = TT + 4;        // per-parity smem entries (incl. float4 overread)
constexpr int JVEC    = 516;           // float4 loads per tile: covers sig[s0-2 .. s0+2061]

// sig[i] = x_ext[i+1] with symmetric pad of 7 each side.
// interior: x[i-6]; left (i<6): x[5-i]; right (i>=N+6): x[2N+5-i]
__device__ __forceinline__ int map_sig(int i) {
    int m = i - 6;
    m = (m < 0) ? (-1 - m) : m;
    m = (m >= N_IN) ? (2 * N_IN - 1 - m) : m;
    return m;
}

__global__ __launch_bounds__(THREADS) void dwt_kernel(const float* __restrict__ x,
                                                      float* __restrict__ out)
{
    // se[i] = sig[s0 + 2i] (even taps), so[i] = sig[s0 + 2i + 1] (odd taps)
    // raw arrays have 1 front-pad slot (for the i = -1 spill of the vector fill)
    // and tail slack; compute reads &se[u] stay 16B-aligned on the raw array +4B?
    // -> se points at raw+1 would misalign reads, so instead we keep se == raw
    //    and let the vector fill write i = 2j-1 (>= -1) into a dedicated pad var.
    __shared__ __align__(16) float se[SLEN + 8];
    __shared__ __align__(16) float so[SLEN + 8];
    __shared__ float pad_sink[2];   // absorbs the i = -1 writes

    const int row = blockIdx.y;
    const int bx  = blockIdx.x;
    const int t0  = bx * TT;
    const float* __restrict__ xr = x + (size_t)row * N_IN;

    const int s0   = 2 * t0;       // first sig index of this tile
    const int base = s0 - 8;       // aligned (mult of 4) vector-load base; sig s0-2

    // ---- vectorized fill: LDG.128, deinterleave in registers ----
    for (int j = threadIdx.x; j < JVEC; j += THREADS) {
        int g = base + 4 * j;
        g = g < 0 ? 0 : g;
        g = g > (N_IN - 4) ? (N_IN - 4) : g;         // clamp: OOB only in edge tiles
        const float4 v = *reinterpret_cast<const float4*>(xr + g);
        // unclamped g corresponds to sig[s0-2+4j .. s0+1+4j]
        const int i = 2 * j - 1;
        float* pe = (i >= 0) ? &se[i] : &pad_sink[0];
        float* po = (i >= 0) ? &so[i] : &pad_sink[1];
        pe[0] = v.x;                 // sig[s0 + 2(2j-1)]
        po[0] = v.y;                 // sig[s0 + 2(2j-1) + 1]
        se[2 * j] = v.z;             // sig[s0 + 4j]
        so[2 * j] = v.w;             // sig[s0 + 4j + 1]
    }
    __syncthreads();

    // ---- boundary fix-up: only first/last tile columns have mirrored /
    //      clamp-corrupted entries, all within the first 8 slots ----
    if ((bx == 0 || bx == TILES - 1) && threadIdx.x < 8) {
        const int i = threadIdx.x;
        se[i] = xr[map_sig(s0 + 2 * i)];
        so[i] = xr[map_sig(s0 + 2 * i + 1)];
    }
    __syncthreads();

    // time-reversed filters (compile-time immediates)
    const float LO[8] = {  0.23037781330885523f,  0.7148465705525415f,
                           0.6308807679295904f,  -0.02798376941698385f,
                          -0.18703481171888114f,  0.030841381835986965f,
                           0.032883011666982945f,-0.010597401784997278f };
    const float HI[8] = { -0.010597401784997278f,-0.032883011666982945f,
                           0.030841381835986965f, 0.18703481171888114f,
                          -0.02798376941698385f, -0.6308807679295904f,
                           0.7148465705525415f,  -0.23037781330885523f };

    const int u = TPT * threadIdx.x;     // local t offset (multiple of 4)

    // conflict-free, 16B-aligned vector loads from smem
    const float4 ev0 = *reinterpret_cast<const float4*>(&se[u]);
    const float4 ev1 = *reinterpret_cast<const float4*>(&se[u + 4]);
    const float4 od0 = *reinterpret_cast<const float4*>(&so[u]);
    const float4 od1 = *reinterpret_cast<const float4*>(&so[u + 4]);
    const float e[8] = { ev0.x, ev0.y, ev0.z, ev0.w, ev1.x, ev1.y, ev1.z, ev1.w };
    const float o[8] = { od0.x, od0.y, od0.z, od0.w, od1.x, od1.y, od1.z, od1.w };

    float ca[TPT], cd[TPT];
    #pragma unroll
    for (int v = 0; v < TPT; v++) {
        float a = 0.f, d = 0.f;
        #pragma unroll
        for (int c = 0; c < 4; c++) {
            a = fmaf(LO[2*c    ], e[v + c], a);
            a = fmaf(LO[2*c + 1], o[v + c], a);
            d = fmaf(HI[2*c    ], e[v + c], d);
            d = fmaf(HI[2*c + 1], o[v + c], d);
        }
        ca[v] = a; cd[v] = d;
    }

    float* __restrict__ orow = out + (size_t)row * OUTROW;
    const int t = t0 + u;
    if (t + 3 < T_OUT) {
        // cA: 8B-aligned float2 stores
        *reinterpret_cast<float2*>(&orow[t    ]) = make_float2(ca[0], ca[1]);
        *reinterpret_cast<float2*>(&orow[t + 2]) = make_float2(ca[2], ca[3]);
        // cD offsets are odd (T_OUT odd) -> scalar stores
        orow[T_OUT + t    ] = cd[0];
        orow[T_OUT + t + 1] = cd[1];
        orow[T_OUT + t + 2] = cd[2];
        orow[T_OUT + t + 3] = cd[3];
    } else {
        #pragma unroll
        for (int v = 0; v < TPT; v++) {
            if (t + v < T_OUT) {
                orow[t + v]         = ca[v];
                orow[T_OUT + t + v] = cd[v];
            }
        }
    }
}

extern "C" void kernel_launch(void* const* d_in, const int* in_sizes, int n_in,
                              void* d_out, int out_size)
{
    const float* x = (const float*)d_in[0];
    float* out = (float*)d_out;
    const int rows = in_sizes[0] / N_IN;   // 4096
    dim3 grid(TILES, rows);
    dwt_kernel<<<grid, THREADS>>>(x, out);
}

// round 6
// speedup vs baseline: 1.4073x; 1.1265x over previous
#include <cuda_runtime.h>
#include <cstdint>

constexpr int N_IN   = 16384;
constexpr int T_OUT  = 8195;           // ((N+13)-8)/2+1
constexpr int OUTROW = 2 * T_OUT;      // 16390

constexpr int THREADS        = 256;
constexpr int WARPS          = THREADS / 32;                       // 8
constexpr int T_PER_WARP     = 64;                                 // 2 t per lane
constexpr int WARPS_PER_ROW  = (T_OUT + T_PER_WARP - 1) / T_PER_WARP;   // 129
constexpr int BLOCKS_PER_ROW = (WARPS_PER_ROW + WARPS - 1) / WARPS;     // 17

// time-reversed filters (compile-time immediates -> FFMA-imm)
__device__ constexpr float LO[8] = {  0.23037781330885523f,  0.7148465705525415f,
                                      0.6308807679295904f,  -0.02798376941698385f,
                                     -0.18703481171888114f,  0.030841381835986965f,
                                      0.032883011666982945f,-0.010597401784997278f };
__device__ constexpr float HI[8] = { -0.010597401784997278f,-0.032883011666982945f,
                                      0.030841381835986965f, 0.18703481171888114f,
                                     -0.02798376941698385f, -0.6308807679295904f,
                                      0.7148465705525415f,  -0.23037781330885523f };

// sig[i] -> x index with symmetric mirror (verified rel_err==0 in R1)
__device__ __forceinline__ int map_sig(int i) {
    int m = i - 6;
    m = (m < 0) ? (-1 - m) : m;
    m = (m >= N_IN) ? (2 * N_IN - 1 - m) : m;
    return m;
}

// scalar mirrored path for the 8 boundary t's per row
__device__ __forceinline__ void slow_t(const float* __restrict__ xr, int t,
                                       float& a, float& d) {
    a = 0.f; d = 0.f;
    #pragma unroll
    for (int j = 0; j < 8; j++) {
        const float s = __ldg(xr + map_sig(2 * t + j));
        a = fmaf(LO[j], s, a);
        d = fmaf(HI[j], s, d);
    }
}

__global__ __launch_bounds__(THREADS) void dwt_kernel(const float* __restrict__ x,
                                                      float* __restrict__ out)
{
    const int row  = blockIdx.y;
    const int wid  = threadIdx.x >> 5;
    const int lane = threadIdx.x & 31;
    const int wir  = blockIdx.x * WARPS + wid;           // warp index within row
    if (wir >= WARPS_PER_ROW) return;                    // uniform whole-warp exit

    const float* __restrict__ xr = x + (size_t)row * N_IN;

    const int t = wir * T_PER_WARP + 2 * lane;           // this lane's t-pair start
    const int b = 2 * t - 8;                             // x index of own float4 (mult of 4)

    // one contiguous 512B LDG.128 per warp (clamped for edges; edges redone scalar)
    const int b0 = min(max(b, 0), N_IN - 4);
    const float4 v = *reinterpret_cast<const float4*>(xr + b0);

    // lanes 30/31: direct loads replacing out-of-warp shfl sources
    float4 m1 = v, m2 = v;
    if (lane >= 30) {
        const int c1 = min(max(b + 4, 0), N_IN - 4);
        const int c2 = min(max(b + 8, 0), N_IN - 4);
        m1 = *reinterpret_cast<const float4*>(xr + c1);
        m2 = *reinterpret_cast<const float4*>(xr + c2);
    }

    // neighbor windows via shuffle crossbar (no L1 data traffic)
    float4 n1, n2;
    n1.x = __shfl_down_sync(0xffffffffu, v.x, 1);
    n1.y = __shfl_down_sync(0xffffffffu, v.y, 1);
    n1.z = __shfl_down_sync(0xffffffffu, v.z, 1);
    n1.w = __shfl_down_sync(0xffffffffu, v.w, 1);
    n2.x = __shfl_down_sync(0xffffffffu, v.x, 2);
    n2.y = __shfl_down_sync(0xffffffffu, v.y, 2);
    n2.z = __shfl_down_sync(0xffffffffu, v.z, 2);
    n2.w = __shfl_down_sync(0xffffffffu, v.w, 2);
    if (lane == 31) n1 = m1;
    if (lane >= 30) n2 = m2;

    // f[j] = sig[2t+j] = x[b+2+j], j = 0..9
    const float f[10] = { v.z, v.w, n1.x, n1.y, n1.z, n1.w,
                          n2.x, n2.y, n2.z, n2.w };

    float ca0 = 0.f, cd0 = 0.f, ca1 = 0.f, cd1 = 0.f;
    #pragma unroll
    for (int j = 0; j < 8; j++) {
        ca0 = fmaf(LO[j], f[j],     ca0);
        cd0 = fmaf(HI[j], f[j],     cd0);
        ca1 = fmaf(LO[j], f[j + 2], ca1);
        cd1 = fmaf(HI[j], f[j + 2], cd1);
    }

    // boundary overwrite (taps mirrored or load base clamped): t in [0,3] U [8191,8194]
    if ((t < 4 || t > 8190) && t < T_OUT)              slow_t(xr, t,     ca0, cd0);
    if ((t + 1 < 4 || t + 1 > 8190) && t + 1 < T_OUT)  slow_t(xr, t + 1, ca1, cd1);

    float* __restrict__ orow = out + (size_t)row * OUTROW;
    if (t + 1 < T_OUT) {
        *reinterpret_cast<float2*>(&orow[t]) = make_float2(ca0, ca1);  // 8B-aligned
        orow[T_OUT + t]     = cd0;
        orow[T_OUT + t + 1] = cd1;
    } else if (t < T_OUT) {
        orow[t]         = ca0;
        orow[T_OUT + t] = cd0;
    }
}

extern "C" void kernel_launch(void* const* d_in, const int* in_sizes, int n_in,
                              void* d_out, int out_size)
{
    const float* x = (const float*)d_in[0];
    float* out = (float*)d_out;
    const int rows = in_sizes[0] / N_IN;   // 4096
    dim3 grid(BLOCKS_PER_ROW, rows);
    dwt_kernel<<<grid, THREADS>>>(x, out);
}

// round 7
// speedup vs baseline: 1.5550x; 1.1050x over previous
#include <cuda_runtime.h>
#include <cstdint>

constexpr int N_IN   = 16384;
constexpr int T_OUT  = 8195;           // ((N+13)-8)/2+1
constexpr int OUTROW = 2 * T_OUT;      // 16390

constexpr int THREADS        = 256;
constexpr int WARPS          = THREADS / 32;                        // 8
constexpr int T_PER_WARP     = 128;                                 // 4 t per lane
constexpr int WARPS_PER_ROW  = (T_OUT + T_PER_WARP - 1) / T_PER_WARP;   // 65
constexpr int BLOCKS_PER_ROW = (WARPS_PER_ROW + WARPS - 1) / WARPS;     // 9

// time-reversed filters (compile-time immediates -> FFMA-imm)
__device__ constexpr float LO[8] = {  0.23037781330885523f,  0.7148465705525415f,
                                      0.6308807679295904f,  -0.02798376941698385f,
                                     -0.18703481171888114f,  0.030841381835986965f,
                                      0.032883011666982945f,-0.010597401784997278f };
__device__ constexpr float HI[8] = { -0.010597401784997278f,-0.032883011666982945f,
                                      0.030841381835986965f, 0.18703481171888114f,
                                     -0.02798376941698385f, -0.6308807679295904f,
                                      0.7148465705525415f,  -0.23037781330885523f };

// sig[i] -> x index with symmetric mirror (verified rel_err==0)
__device__ __forceinline__ int map_sig(int i) {
    int m = i - 6;
    m = (m < 0) ? (-1 - m) : m;
    m = (m >= N_IN) ? (2 * N_IN - 1 - m) : m;
    return m;
}

// scalar mirrored path for the 8 boundary t's per row
__device__ __forceinline__ void slow_t(const float* __restrict__ xr, int t,
                                       float& a, float& d) {
    a = 0.f; d = 0.f;
    #pragma unroll
    for (int j = 0; j < 8; j++) {
        const float s = __ldg(xr + map_sig(2 * t + j));
        a = fmaf(LO[j], s, a);
        d = fmaf(HI[j], s, d);
    }
}

__global__ __launch_bounds__(THREADS) void dwt_kernel(const float* __restrict__ x,
                                                      float* __restrict__ out)
{
    const int row  = blockIdx.y;
    const int wid  = threadIdx.x >> 5;
    const int lane = threadIdx.x & 31;
    const int wir  = blockIdx.x * WARPS + wid;           // warp index within row
    if (wir >= WARPS_PER_ROW) return;                    // uniform whole-warp exit

    const float* __restrict__ xr = x + (size_t)row * N_IN;

    const int t = wir * T_PER_WARP + 4 * lane;           // this lane's 4-t start
    const int b = 2 * t - 8;                             // own data base (mult of 4)

    // own 8 floats: two aligned LDG.128 (512B x2 contiguous per warp)
    const int b0 = min(max(b,     0), N_IN - 4);
    const int b1 = min(max(b + 4, 0), N_IN - 4);
    const float4 v0 = *reinterpret_cast<const float4*>(xr + b0);
    const float4 v1 = *reinterpret_cast<const float4*>(xr + b1);

    // lane 31: direct loads replacing out-of-warp shfl sources
    float4 p0 = v0, p1 = v1;
    if (lane == 31) {
        const int c0 = min(max(b +  8, 0), N_IN - 4);
        const int c1 = min(max(b + 12, 0), N_IN - 4);
        p0 = *reinterpret_cast<const float4*>(xr + c0);
        p1 = *reinterpret_cast<const float4*>(xr + c1);
    }

    // neighbor lane's 8 floats via shuffle crossbar
    float4 n0, n1;
    n0.x = __shfl_down_sync(0xffffffffu, v0.x, 1);
    n0.y = __shfl_down_sync(0xffffffffu, v0.y, 1);
    n0.z = __shfl_down_sync(0xffffffffu, v0.z, 1);
    n0.w = __shfl_down_sync(0xffffffffu, v0.w, 1);
    n1.x = __shfl_down_sync(0xffffffffu, v1.x, 1);
    n1.y = __shfl_down_sync(0xffffffffu, v1.y, 1);
    n1.z = __shfl_down_sync(0xffffffffu, v1.z, 1);
    n1.w = __shfl_down_sync(0xffffffffu, v1.w, 1);
    if (lane == 31) { n0 = p0; n1 = p1; }

    // f[j] = sig[2t+j] = x[b+2+j], j = 0..13
    const float f[14] = { v0.z, v0.w, v1.x, v1.y, v1.z, v1.w,
                          n0.x, n0.y, n0.z, n0.w, n1.x, n1.y, n1.z, n1.w };

    float ca[4], cd[4];
    #pragma unroll
    for (int v = 0; v < 4; v++) {
        float a = 0.f, d = 0.f;
        #pragma unroll
        for (int j = 0; j < 8; j++) {
            a = fmaf(LO[j], f[2 * v + j], a);
            d = fmaf(HI[j], f[2 * v + j], d);
        }
        ca[v] = a; cd[v] = d;
    }

    // boundary overwrite (mirrored taps or clamped base): t in [0,3] U [8191,8194]
    if (t < 4 || t + 3 > 8190) {
        #pragma unroll
        for (int v = 0; v < 4; v++) {
            const int tv = t + v;
            if ((tv < 4 || tv > 8190) && tv < T_OUT) slow_t(xr, tv, ca[v], cd[v]);
        }
    }

    float* __restrict__ orow = out + (size_t)row * OUTROW;
    if (t + 3 < T_OUT) {
        // cA: 8B-aligned float2 stores
        *reinterpret_cast<float2*>(&orow[t    ]) = make_float2(ca[0], ca[1]);
        *reinterpret_cast<float2*>(&orow[t + 2]) = make_float2(ca[2], ca[3]);
        // cD base is odd -> scalar stores
        orow[T_OUT + t    ] = cd[0];
        orow[T_OUT + t + 1] = cd[1];
        orow[T_OUT + t + 2] = cd[2];
        orow[T_OUT + t + 3] = cd[3];
    } else {
        #pragma unroll
        for (int v = 0; v < 4; v++) {
            if (t + v < T_OUT) {
                orow[t + v]         = ca[v];
                orow[T_OUT + t + v] = cd[v];
            }
        }
    }
}

extern "C" void kernel_launch(void* const* d_in, const int* in_sizes, int n_in,
                              void* d_out, int out_size)
{
    const float* x = (const float*)d_in[0];
    float* out = (float*)d_out;
    const int rows = in_sizes[0] / N_IN;   // 4096
    dim3 grid(BLOCKS_PER_ROW, rows);
    dwt_kernel<<<grid, THREADS>>>(x, out);
}

// round 8
// speedup vs baseline: 1.5860x; 1.0199x over previous
#include <cuda_runtime.h>
#include <cstdint>

constexpr int N_IN   = 16384;
constexpr int T_OUT  = 8195;           // ((N+13)-8)/2+1
constexpr int OUTROW = 2 * T_OUT;      // 16390

constexpr int THREADS        = 256;
constexpr int WARPS          = THREADS / 32;                        // 8
constexpr int T_PER_WARP     = 128;                                 // 4 t per lane
constexpr int WARPS_PER_ROW  = (T_OUT + T_PER_WARP - 1) / T_PER_WARP;   // 65
constexpr int BLOCKS_PER_ROW = (WARPS_PER_ROW + WARPS - 1) / WARPS;     // 9

// time-reversed filters (compile-time immediates -> FFMA-imm)
__device__ constexpr float LO[8] = {  0.23037781330885523f,  0.7148465705525415f,
                                      0.6308807679295904f,  -0.02798376941698385f,
                                     -0.18703481171888114f,  0.030841381835986965f,
                                      0.032883011666982945f,-0.010597401784997278f };
__device__ constexpr float HI[8] = { -0.010597401784997278f,-0.032883011666982945f,
                                      0.030841381835986965f, 0.18703481171888114f,
                                     -0.02798376941698385f, -0.6308807679295904f,
                                      0.7148465705525415f,  -0.23037781330885523f };

// sig[i] -> x index with symmetric mirror (verified rel_err==0)
__device__ __forceinline__ int map_sig(int i) {
    int m = i - 6;
    m = (m < 0) ? (-1 - m) : m;
    m = (m >= N_IN) ? (2 * N_IN - 1 - m) : m;
    return m;
}

// scalar mirrored path for the 8 boundary t's per row
__device__ __forceinline__ void slow_t(const float* __restrict__ xr, int t,
                                       float& a, float& d) {
    a = 0.f; d = 0.f;
    #pragma unroll
    for (int j = 0; j < 8; j++) {
        const float s = __ldg(xr + map_sig(2 * t + j));
        a = fmaf(LO[j], s, a);
        d = fmaf(HI[j], s, d);
    }
}

__global__ __launch_bounds__(THREADS) void dwt_kernel(const float* __restrict__ x,
                                                      float* __restrict__ out)
{
    const int row  = blockIdx.y;
    const int wid  = threadIdx.x >> 5;
    const int lane = threadIdx.x & 31;
    const int wir  = blockIdx.x * WARPS + wid;           // warp index within row
    if (wir >= WARPS_PER_ROW) return;                    // uniform whole-warp exit

    const float* __restrict__ xr = x + (size_t)row * N_IN;

    const int t = wir * T_PER_WARP + 4 * lane;           // this lane's 4-t start
    const int b = 2 * t - 8;                             // own data base (mult of 4)

    // own 8 floats: two aligned LDG.128 (contiguous 1KB per warp)
    const int b0 = min(max(b,     0), N_IN - 4);
    const int b1 = min(max(b + 4, 0), N_IN - 4);
    const float4 v0 = *reinterpret_cast<const float4*>(xr + b0);
    const float4 v1 = *reinterpret_cast<const float4*>(xr + b1);

    // lane 31: direct loads replacing out-of-warp shfl sources
    float4 p0 = v0, p1 = v1;
    if (lane == 31) {
        const int c0 = min(max(b +  8, 0), N_IN - 4);
        const int c1 = min(max(b + 12, 0), N_IN - 4);
        p0 = *reinterpret_cast<const float4*>(xr + c0);
        p1 = *reinterpret_cast<const float4*>(xr + c1);
    }

    // neighbor lane's 8 floats via shuffle crossbar
    float4 n0, n1;
    n0.x = __shfl_down_sync(0xffffffffu, v0.x, 1);
    n0.y = __shfl_down_sync(0xffffffffu, v0.y, 1);
    n0.z = __shfl_down_sync(0xffffffffu, v0.z, 1);
    n0.w = __shfl_down_sync(0xffffffffu, v0.w, 1);
    n1.x = __shfl_down_sync(0xffffffffu, v1.x, 1);
    n1.y = __shfl_down_sync(0xffffffffu, v1.y, 1);
    n1.z = __shfl_down_sync(0xffffffffu, v1.z, 1);
    n1.w = __shfl_down_sync(0xffffffffu, v1.w, 1);
    if (lane == 31) { n0 = p0; n1 = p1; }

    // f[j] = sig[2t+j] = x[b+2+j], j = 0..13
    const float f[14] = { v0.z, v0.w, v1.x, v1.y, v1.z, v1.w,
                          n0.x, n0.y, n0.z, n0.w, n1.x, n1.y, n1.z, n1.w };

    float ca0=0.f, ca1=0.f, ca2=0.f, ca3=0.f;
    float cd0=0.f, cd1=0.f, cd2=0.f, cd3=0.f;
    #pragma unroll
    for (int j = 0; j < 8; j++) {
        ca0 = fmaf(LO[j], f[j    ], ca0);  cd0 = fmaf(HI[j], f[j    ], cd0);
        ca1 = fmaf(LO[j], f[j + 2], ca1);  cd1 = fmaf(HI[j], f[j + 2], cd1);
        ca2 = fmaf(LO[j], f[j + 4], ca2);  cd2 = fmaf(HI[j], f[j + 4], cd2);
        ca3 = fmaf(LO[j], f[j + 6], ca3);  cd3 = fmaf(HI[j], f[j + 6], cd3);
    }

    // boundary overwrite (mirrored taps or clamped base): t in [0,3] U [8191,8194]
    if (t < 4 || t + 3 > 8190) {
        if ((t     < 4 || t     > 8190) && t     < T_OUT) slow_t(xr, t,     ca0, cd0);
        if ((t + 1 < 4 || t + 1 > 8190) && t + 1 < T_OUT) slow_t(xr, t + 1, ca1, cd1);
        if ((t + 2 < 4 || t + 2 > 8190) && t + 2 < T_OUT) slow_t(xr, t + 2, ca2, cd2);
        if ((t + 3 < 4 || t + 3 > 8190) && t + 3 > 8190 && t + 3 < T_OUT) slow_t(xr, t + 3, ca3, cd3);
        else if (t + 3 < 4) slow_t(xr, t + 3, ca3, cd3);
    }

    float* __restrict__ orow = out + (size_t)row * OUTROW;
    const bool full_warp = (wir * T_PER_WARP + T_PER_WARP) <= T_OUT;   // warp-uniform

    if (full_warp) {
        // ---- aligned, shuffle-shifted STG.128 stores ----
        float* __restrict__ gA = orow + t;            // elem index ≡ {0,2} mod 4
        float* __restrict__ gD = orow + T_OUT + t;    // elem index ≡ {3,1} mod 4

        if (((size_t)row & 1) == 0) {
            // cA aligned directly
            *reinterpret_cast<float4*>(gA) = make_float4(ca0, ca1, ca2, ca3);
            // cD: shift 1 -> {cd1,cd2,cd3,next.cd0} at gD+1
            const float nd0 = __shfl_down_sync(0xffffffffu, cd0, 1);
            if (lane < 31) {
                *reinterpret_cast<float4*>(gD + 1) = make_float4(cd1, cd2, cd3, nd0);
            } else {
                gD[1] = cd1; gD[2] = cd2; gD[3] = cd3;
            }
            if (lane == 0) gD[0] = cd0;
        } else {
            // cA: shift 2 -> {ca2,ca3,next.ca0,next.ca1} at gA+2
            const float na0 = __shfl_down_sync(0xffffffffu, ca0, 1);
            const float na1 = __shfl_down_sync(0xffffffffu, ca1, 1);
            if (lane < 31) {
                *reinterpret_cast<float4*>(gA + 2) = make_float4(ca2, ca3, na0, na1);
            } else {
                gA[2] = ca2; gA[3] = ca3;
            }
            if (lane == 0) { gA[0] = ca0; gA[1] = ca1; }
            // cD: shift 3 -> {cd3,next.cd0,next.cd1,next.cd2} at gD+3
            const float nd0 = __shfl_down_sync(0xffffffffu, cd0, 1);
            const float nd1 = __shfl_down_sync(0xffffffffu, cd1, 1);
            const float nd2 = __shfl_down_sync(0xffffffffu, cd2, 1);
            if (lane < 31) {
                *reinterpret_cast<float4*>(gD + 3) = make_float4(cd3, nd0, nd1, nd2);
            } else {
                gD[3] = cd3;
            }
            if (lane == 0) { gD[0] = cd0; gD[1] = cd1; gD[2] = cd2; }
        }
    } else {
        // tail warp: scalar bounded stores
        const float ca[4] = { ca0, ca1, ca2, ca3 };
        const float cd[4] = { cd0, cd1, cd2, cd3 };
        #pragma unroll
        for (int v = 0; v < 4; v++) {
            if (t + v < T_OUT) {
                orow[t + v]         = ca[v];
                orow[T_OUT + t + v] = cd[v];
            }
        }
    }
}

extern "C" void kernel_launch(void* const* d_in, const int* in_sizes, int n_in,
                              void* d_out, int out_size)
{
    const float* x = (const float*)d_in[0];
    float* out = (float*)d_out;
    const int rows = in_sizes[0] / N_IN;   // 4096
    dim3 grid(BLOCKS_PER_ROW, rows);
    dwt_kernel<<<grid, THREADS>>>(x, out);
}